// round 13
// baseline (speedup 1.0000x reference)
#include <cuda_runtime.h>
#include <math.h>

#define NB 8       // batch
#define NS 5       // max slabs reachable (spans in [0,5])
#define NSFULL 6   // slab dimension of the input tensor
#define NM 64      // M
#define NV 32000   // vocab
#define NT 8       // template length
#define NTH 4      // t per block-half
#define VSPLIT 10
#define CHUNK  (NV / VSPLIT)    // 3200 floats
#define CHUNK4 (CHUNK / 4)      // 800 float4
#define NITER_A ((CHUNK4 + 63) / 64)     // 13 (64-thread half strides)
#define NITER_C ((CHUNK4 + 127) / 128)   // 7
#define SSTRIDE4 ((NM * NV) / 4)         // float4 stride between slabs
#define NBLK   (NM * 2 * VSPLIT)         // 1280 blocks, all co-resident @9/SM
#define NPAIR  (NB / 2)                  // 4 batch pairs

// tiny scratch (__device__ globals, no runtime allocation)
__device__ float    g_pmax[NB * NT * NM * VSPLIT];  // per-chunk partial max
__device__ float    g_out0[NB * NT * NM];           // out[b,t,m,0] (+pad)
__device__ unsigned g_count;                        // barrier arrivals (self-resets)
__device__ unsigned g_sense;                        // barrier sense (monotonic)

// ---------------------------------------------------------------------------
// Grid-wide barrier. launch_bounds(128,9) forces regs<=56 so 148*9=1332>=1280
// blocks are co-resident. Sense monotonic (replay-safe); count self-resets.
// ---------------------------------------------------------------------------
__device__ __forceinline__ void grid_barrier() {
    __syncthreads();
    __threadfence();
    if (threadIdx.x == 0) {
        const unsigned s0 = *(volatile unsigned*)&g_sense;
        const unsigned v  = atomicAdd(&g_count, 1);
        if (v == NBLK - 1) {
            g_count = 0;
            __threadfence();
            atomicAdd(&g_sense, 1);
        } else {
            while (*(volatile unsigned*)&g_sense == s0) { __nanosleep(64); }
        }
    }
    __syncthreads();
    __threadfence();
}

// ---------------------------------------------------------------------------
// Phase A body, compile-time S, half-block (64 threads) covers the chunk for
// its 4 t values. Weight regs: 4x5 = 20 per thread.
// ---------------------------------------------------------------------------
template <int S>
__device__ __forceinline__ void phase_a_body(
    const float4* __restrict__ p0, int hid,
    const float (&sw)[NTH][NS], float (&maxv)[NTH]) {

    #pragma unroll
    for (int t = 0; t < NTH; t++) maxv[t] = -INFINITY;

    #pragma unroll 2
    for (int j = 0; j < NITER_A; j++) {
        const int i = hid + j * 64;
        if (i < CHUNK4) {
            float4 x[S > 0 ? S : 1];
            #pragma unroll
            for (int s = 0; s < S; s++) x[s] = p0[i + s * SSTRIDE4];

            #pragma unroll
            for (int t = 0; t < NTH; t++) {
                float ax = 0.f, ay = 0.f, az = 0.f, aw = 0.f;
                #pragma unroll
                for (int s = 0; s < S; s++) {
                    const float wv = sw[t][s];
                    ax = fmaf(wv, x[s].x, ax);
                    ay = fmaf(wv, x[s].y, ay);
                    az = fmaf(wv, x[s].z, az);
                    aw = fmaf(wv, x[s].w, aw);
                }
                maxv[t] = fmaxf(maxv[t], fmaxf(fmaxf(ax, ay), fmaxf(az, aw)));
            }
        }
    }
}

// ---------------------------------------------------------------------------
// Phase C body, compile-time S, streaming stores (full 128 threads).
// ---------------------------------------------------------------------------
template <int S>
__device__ __forceinline__ void phase_c_body(
    const float4* __restrict__ p0, float4* __restrict__ dst,
    const float (&ws)[NS], float w0, int ml, int chunk) {

    const int tid = threadIdx.x;
    #pragma unroll 2
    for (int j = 0; j < NITER_C; j++) {
        const int i = tid + j * 128;
        if (i < CHUNK4) {
            float4 x[S > 0 ? S : 1];
            #pragma unroll
            for (int s = 0; s < S; s++) x[s] = p0[i + s * SSTRIDE4];

            float4 acc = make_float4(0.f, 0.f, 0.f, 0.f);
            #pragma unroll
            for (int s = 0; s < S; s++) {
                const float wv = ws[s];
                acc.x = fmaf(wv, x[s].x, acc.x);
                acc.y = fmaf(wv, x[s].y, acc.y);
                acc.z = fmaf(wv, x[s].z, acc.z);
                acc.w = fmaf(wv, x[s].w, acc.w);
            }
            if (chunk == 0 && i == 0 && ml == 0) acc.x += w0;  // pad one-hot
            __stcs(dst + i, acc);
        }
    }
}

// ---------------------------------------------------------------------------
// Fused persistent kernel (t split across block halves):
//   A_p -> barrier -> C_p per batch pair.
// argmax==0  <=>  out[v=0] attains the max (argmax ties go to index 0)
// ---------------------------------------------------------------------------
__global__ void __launch_bounds__(128, 9)
fused_kernel(const float* __restrict__ in, const float* __restrict__ tmpl,
             const int* __restrict__ spans, float* __restrict__ out) {
    const int m     = blockIdx.x;       // row index in A, output row j in C
    const int yb    = blockIdx.y;       // 0/1 within the pair
    const int chunk = blockIdx.z;
    const int tid   = threadIdx.x;
    const int wid   = tid >> 5;
    const int lane  = tid & 31;
    const int half  = wid >> 1;         // 0: t=0..3, 1: t=4..7
    const int hid   = tid & 63;         // thread index within half

    __shared__ float spart[4][NTH];     // per-warp max partials
    __shared__ unsigned char sflags[NT * NM];
    __shared__ unsigned char slen[NT];
    __shared__ short         srow[NM];

    for (int p = 0; p < NPAIR; p++) {
        const int b = 2 * p + yb;
        __syncthreads();                // protect shared arrays across pairs

        const int S = __ldg(&spans[b]);

        // this half's weights: t = half*4 + 0..3, s columns 1..5 of tmpl
        float sw[NTH][NS];
        #pragma unroll
        for (int t = 0; t < NTH; t++)
            #pragma unroll
            for (int s = 0; s < NS; s++)
                sw[t][s] = __ldg(&tmpl[((size_t)b * NT + half * NTH + t)
                                       * (NSFULL + 1) + s + 1]);

        const float4* pa = reinterpret_cast<const float4*>(
            in + ((size_t)b * NSFULL * NM + m) * NV + chunk * CHUNK);

        // ---- phase A (each half covers the whole chunk for its 4 t) ----
        float maxv[NTH];
        switch (S) {
            case 0: phase_a_body<0>(pa, hid, sw, maxv); break;
            case 1: phase_a_body<1>(pa, hid, sw, maxv); break;
            case 2: phase_a_body<2>(pa, hid, sw, maxv); break;
            case 3: phase_a_body<3>(pa, hid, sw, maxv); break;
            case 4: phase_a_body<4>(pa, hid, sw, maxv); break;
            default: phase_a_body<5>(pa, hid, sw, maxv); break;
        }

        #pragma unroll
        for (int t = 0; t < NTH; t++) {
            float v = maxv[t];
            #pragma unroll
            for (int off = 16; off > 0; off >>= 1)
                v = fmaxf(v, __shfl_xor_sync(0xFFFFFFFFu, v, off));
            maxv[t] = v;
        }
        if (lane == 0) {
            #pragma unroll
            for (int t = 0; t < NTH; t++) spart[wid][t] = maxv[t];
        }
        __syncthreads();
        if (tid < NT) {                  // tid = h*4 + t
            const int h = tid >> 2, t = tid & 3;
            const float mx = fmaxf(spart[2 * h][t], spart[2 * h + 1][t]);
            g_pmax[(((size_t)b * NT + (h * NTH + t)) * NM + m) * VSPLIT + chunk] = mx;
        }

        // cold epilogue: out[b,t,m,0] (dot + pad), chunk 0; thread 0 per half
        if (chunk == 0 && hid == 0) {
            float x0[NS];
            for (int s = 0; s < S; s++)
                x0[s] = __ldg(reinterpret_cast<const float*>(pa + s * SSTRIDE4));
            #pragma unroll
            for (int t = 0; t < NTH; t++) {
                float v = 0.f;
                for (int s = 0; s < S; s++) v = fmaf(sw[t][s], x0[s], v);
                if (m == 0)
                    v += __ldg(&tmpl[((size_t)b * NT + half * NTH + t) * (NSFULL + 1)]);
                g_out0[((size_t)b * NT + half * NTH + t) * NM + m] = v;
            }
        }

        // ---- all blocks' maxes must land before anyone scans ----
        grid_barrier();

        // ---- phase C: flags + scan (redundant per block, L2-hot) ----
        #pragma unroll
        for (int k = 0; k < 4; k++) {
            const int tm  = tid + 128 * k;               // t*64 + mm
            const int idx = b * NT * NM + tm;
            const float* pm = &g_pmax[(size_t)idx * VSPLIT];
            float mx = -INFINITY;
            #pragma unroll
            for (int c = 0; c < VSPLIT; c++) mx = fmaxf(mx, __ldcg(pm + c));
            sflags[tm] = (__ldcg(&g_out0[idx]) >= mx) ? 1 : 0;
        }
        __syncthreads();

        if (tid < NT) {   // first-zero position per t
            int len = NM;
            for (int mm = 0; mm < NM; mm++)
                if (sflags[tid * NM + mm]) { len = mm; break; }
            slen[tid] = (unsigned char)len;
        }
        __syncthreads();

        if (tid == 0) {   // sequential scan -> row map
            for (int q = 0; q < NM; q++) srow[q] = -1;
            int idx = 0;
            for (int t = 0; t < NT; t++) {
                int len = slen[t];
                if (len > NM - idx) len = NM - idx;
                for (int k = 0; k < len; k++)
                    srow[idx + k] = (short)((t << 8) | k);
                idx += len;
            }
        }
        __syncthreads();

        // ---- phase C: materialize this block's output row (j = m) ----
        float4* dst = reinterpret_cast<float4*>(
            out + ((size_t)b * NM + m) * NV + chunk * CHUNK);
        const int code = srow[m];

        if (code < 0) {
            const float4 z = make_float4(0.f, 0.f, 0.f, 0.f);
            #pragma unroll 2
            for (int jj = 0; jj < NITER_C; jj++) {
                const int i = tid + jj * 128;
                if (i < CHUNK4) __stcs(dst + i, z);
            }
        } else {
            const int t  = code >> 8;
            const int ml = code & 255;

            float ws[NS];
            #pragma unroll
            for (int s = 0; s < NS; s++)
                ws[s] = __ldg(&tmpl[((size_t)b * NT + t) * (NSFULL + 1) + s + 1]);
            const float w0 = __ldg(&tmpl[((size_t)b * NT + t) * (NSFULL + 1)]);

            const float4* pc = reinterpret_cast<const float4*>(
                in + ((size_t)b * NSFULL * NM + ml) * NV + chunk * CHUNK);

            switch (S) {
                case 0: phase_c_body<0>(pc, dst, ws, w0, ml, chunk); break;
                case 1: phase_c_body<1>(pc, dst, ws, w0, ml, chunk); break;
                case 2: phase_c_body<2>(pc, dst, ws, w0, ml, chunk); break;
                case 3: phase_c_body<3>(pc, dst, ws, w0, ml, chunk); break;
                case 4: phase_c_body<4>(pc, dst, ws, w0, ml, chunk); break;
                default: phase_c_body<5>(pc, dst, ws, w0, ml, chunk); break;
            }
        }
        // no barrier before next A: g_pmax/g_out0 indices disjoint across
        // pairs; shared arrays protected by loop-top __syncthreads.
    }
}

// ---------------------------------------------------------------------------
extern "C" void kernel_launch(void* const* d_in, const int* in_sizes, int n_in,
                              void* d_out, int out_size) {
    const float* in    = (const float*)d_in[0];  // [8,6,64,32000] f32
    const float* tmpl  = (const float*)d_in[1];  // [8,8,7] f32
    const int*   spans = (const int*)d_in[2];    // [8] i32
    float*       out   = (float*)d_out;          // [8,64,32000] f32

    dim3 grid(NM, 2, VSPLIT);  // 1280 blocks, all co-resident (9/SM cap)
    fused_kernel<<<grid, 128>>>(in, tmpl, spans, out);
}

// round 14
// speedup vs baseline: 1.9336x; 1.9336x over previous
#include <cuda_runtime.h>
#include <math.h>

#define NB 8       // batch
#define NS 5       // max slabs reachable (spans in [0,5])
#define NSFULL 6   // slab dimension of the input tensor
#define NM 64      // M
#define NV 32000   // vocab
#define NT 8       // template length
#define VSPLIT 8
#define CHUNK  (NV / VSPLIT)   // 4000 floats
#define CHUNK4 (CHUNK / 4)     // 1000 float4
#define NITER  ((CHUNK4 + 127) / 128)   // 8
#define SSTRIDE4 ((NM * NV) / 4)        // float4 stride between slabs
#define NBLK   1024                     // all co-resident (128 thr, <=7/SM)
#define NPAIR  (NB / 2)                 // 4 batch pairs

// tiny scratch (__device__ globals, no runtime allocation)
__device__ float    g_pmax[NB * NT * NM * VSPLIT];  // per-chunk partial max
__device__ float    g_out0[NB * NT * NM];           // out[b,t,m,0] (+pad)
__device__ unsigned g_count;                        // barrier arrivals (self-resets)
__device__ unsigned g_sense;                        // barrier sense (monotonic)

// ---------------------------------------------------------------------------
// Grid-wide barrier (all NBLK blocks co-resident; launch_bounds(128,7) =>
// 148*7 = 1036 >= 1024). Sense monotonic (replay-safe); count self-resets.
// ---------------------------------------------------------------------------
__device__ __forceinline__ void grid_barrier() {
    __syncthreads();
    __threadfence();
    if (threadIdx.x == 0) {
        const unsigned s0 = *(volatile unsigned*)&g_sense;
        const unsigned v  = atomicAdd(&g_count, 1);
        if (v == NBLK - 1) {
            g_count = 0;
            __threadfence();
            atomicAdd(&g_sense, 1);
        } else {
            while (*(volatile unsigned*)&g_sense == s0) { __nanosleep(64); }
        }
    }
    __syncthreads();
    __threadfence();
}

// ---------------------------------------------------------------------------
// Phase A body, compile-time S: per-(b,m,chunk) max over v for each t, AND
// speculative store of the t=0 values to the output buffer (the scan maps
// row m -> (t=0, ml=m) unless an argmax==0 occurs, which is fixed later).
// ---------------------------------------------------------------------------
template <int S>
__device__ __forceinline__ void phase_a_body(
    const float4* __restrict__ p0, float4* __restrict__ spec_dst,
    int m, int chunk,
    const float (&sw)[NT][NS], const float (&sw0)[NT], float (&maxv)[NT]) {

    const int tid = threadIdx.x;
    #pragma unroll
    for (int t = 0; t < NT; t++) maxv[t] = -INFINITY;

    #pragma unroll 2
    for (int j = 0; j < NITER; j++) {
        const int i = tid + j * 128;
        if (i < CHUNK4) {
            float4 x[S > 0 ? S : 1];
            #pragma unroll
            for (int s = 0; s < S; s++) x[s] = p0[i + s * SSTRIDE4];

            #pragma unroll
            for (int t = 0; t < NT; t++) {
                float ax = 0.f, ay = 0.f, az = 0.f, aw = 0.f;
                #pragma unroll
                for (int s = 0; s < S; s++) {
                    const float wv = sw[t][s];
                    ax = fmaf(wv, x[s].x, ax);
                    ay = fmaf(wv, x[s].y, ay);
                    az = fmaf(wv, x[s].z, az);
                    aw = fmaf(wv, x[s].w, aw);
                }
                maxv[t] = fmaxf(maxv[t], fmaxf(fmaxf(ax, ay), fmaxf(az, aw)));
                if (t == 0) {   // speculative t=0 output (pad added at v==0)
                    float sx = ax;
                    if (chunk == 0 && i == 0 && m == 0) sx += sw0[0];
                    __stcs(spec_dst + i, make_float4(sx, ay, az, aw));
                }
            }
        }
    }

    // cold epilogue: out[b,t,m,0] (dot + pad one-hot) -> g_out0 caller-side
}

// ---------------------------------------------------------------------------
// Phase C rewrite body, compile-time S, streaming stores (fix-up only).
// ---------------------------------------------------------------------------
template <int S>
__device__ __forceinline__ void phase_c_body(
    const float4* __restrict__ p0, float4* __restrict__ dst,
    const float (&ws)[NS], float w0, int ml, int chunk) {

    const int tid = threadIdx.x;
    #pragma unroll 2
    for (int j = 0; j < NITER; j++) {
        const int i = tid + j * 128;
        if (i < CHUNK4) {
            float4 x[S > 0 ? S : 1];
            #pragma unroll
            for (int s = 0; s < S; s++) x[s] = p0[i + s * SSTRIDE4];

            float4 acc = make_float4(0.f, 0.f, 0.f, 0.f);
            #pragma unroll
            for (int s = 0; s < S; s++) {
                const float wv = ws[s];
                acc.x = fmaf(wv, x[s].x, acc.x);
                acc.y = fmaf(wv, x[s].y, acc.y);
                acc.z = fmaf(wv, x[s].z, acc.z);
                acc.w = fmaf(wv, x[s].w, acc.w);
            }
            if (chunk == 0 && i == 0 && ml == 0) acc.x += w0;  // pad one-hot
            __stcs(dst + i, acc);
        }
    }
}

// ---------------------------------------------------------------------------
// Fused persistent kernel:
//   A (all batches, speculative t=0 store) -> ONE barrier -> scan + fix-up.
// argmax==0  <=>  out[v=0] attains the max (argmax ties go to index 0)
// ---------------------------------------------------------------------------
__global__ void __launch_bounds__(128, 7)
fused_kernel(const float* __restrict__ in, const float* __restrict__ tmpl,
             const int* __restrict__ spans, float* __restrict__ out) {
    const int m     = blockIdx.x;   // row index in A, output row j in C
    const int yb    = blockIdx.y;   // 0/1 within the pair
    const int chunk = blockIdx.z;
    const int tid   = threadIdx.x;

    __shared__ float ssw[NT][NS];
    __shared__ float ssw0[NT];
    __shared__ int   sS;
    __shared__ float spart[4][NT];
    __shared__ unsigned char sflags[NT * NM];
    __shared__ unsigned char slen[NT];
    __shared__ short         srow[NM];

    // ================= phase A: all batches (4 pairs) =================
    for (int p = 0; p < NPAIR; p++) {
        const int b = 2 * p + yb;
        __syncthreads();   // protect shared arrays across iterations

        if (tid == 0) sS = spans[b];
        if (tid < NT * NSFULL) {
            int t = tid / NSFULL, s = tid % NSFULL;
            float v = tmpl[((size_t)b * NT + t) * (NSFULL + 1) + s];
            if (s == 0) ssw0[t] = v;
            else        ssw[t][s - 1] = v;
        }
        __syncthreads();
        const int S = sS;

        float sw[NT][NS], sw0[NT];
        #pragma unroll
        for (int t = 0; t < NT; t++) {
            sw0[t] = ssw0[t];
            #pragma unroll
            for (int s = 0; s < NS; s++) sw[t][s] = ssw[t][s];
        }

        const float4* pa = reinterpret_cast<const float4*>(
            in + ((size_t)b * NSFULL * NM + m) * NV + chunk * CHUNK);
        float4* spec = reinterpret_cast<float4*>(
            out + ((size_t)b * NM + m) * NV + chunk * CHUNK);

        float maxv[NT];
        switch (S) {
            case 0: phase_a_body<0>(pa, spec, m, chunk, sw, sw0, maxv); break;
            case 1: phase_a_body<1>(pa, spec, m, chunk, sw, sw0, maxv); break;
            case 2: phase_a_body<2>(pa, spec, m, chunk, sw, sw0, maxv); break;
            case 3: phase_a_body<3>(pa, spec, m, chunk, sw, sw0, maxv); break;
            case 4: phase_a_body<4>(pa, spec, m, chunk, sw, sw0, maxv); break;
            default: phase_a_body<5>(pa, spec, m, chunk, sw, sw0, maxv); break;
        }

        #pragma unroll
        for (int t = 0; t < NT; t++) {
            float v = maxv[t];
            #pragma unroll
            for (int off = 16; off > 0; off >>= 1)
                v = fmaxf(v, __shfl_xor_sync(0xFFFFFFFFu, v, off));
            maxv[t] = v;
        }
        const int warp = tid >> 5, lane = tid & 31;
        if (lane == 0) {
            #pragma unroll
            for (int t = 0; t < NT; t++) spart[warp][t] = maxv[t];
        }
        __syncthreads();
        if (tid < NT) {
            const int t = tid;
            float mx = fmaxf(fmaxf(spart[0][t], spart[1][t]),
                             fmaxf(spart[2][t], spart[3][t]));
            g_pmax[(((size_t)b * NT + t) * NM + m) * VSPLIT + chunk] = mx;
        }

        // cold epilogue: out0[b,t,m] = dot at v=0 (+ pad if m==0)
        if (chunk == 0 && tid == 0) {
            float x0[NS];
            for (int s = 0; s < S; s++)
                x0[s] = __ldg(reinterpret_cast<const float*>(pa + s * SSTRIDE4));
            #pragma unroll
            for (int t = 0; t < NT; t++) {
                float v = 0.f;
                for (int s = 0; s < S; s++) v = fmaf(sw[t][s], x0[s], v);
                if (m == 0) v += sw0[t];
                g_out0[((size_t)b * NT + t) * NM + m] = v;
            }
        }
    }

    // ---- single barrier: all maxes + speculative stores complete ----
    grid_barrier();

    // ================= phase C: scan + fix-up per batch =================
    for (int p = 0; p < NPAIR; p++) {
        const int b = 2 * p + yb;
        __syncthreads();   // protect shared arrays across iterations

        // flags for this b (L2-hot partials)
        #pragma unroll
        for (int k = 0; k < 4; k++) {
            const int tm  = tid + 128 * k;               // t*64 + mm
            const int idx = b * NT * NM + tm;
            const float4* pm =
                reinterpret_cast<const float4*>(&g_pmax[(size_t)idx * VSPLIT]);
            const float4 a = __ldcg(pm), c = __ldcg(pm + 1);
            float mx = fmaxf(fmaxf(fmaxf(a.x, a.y), fmaxf(a.z, a.w)),
                             fmaxf(fmaxf(c.x, c.y), fmaxf(c.z, c.w)));
            sflags[tm] = (__ldcg(&g_out0[idx]) >= mx) ? 1 : 0;
        }
        __syncthreads();

        if (tid < NT) {   // first-zero position per t
            int len = NM;
            for (int mm = 0; mm < NM; mm++)
                if (sflags[tid * NM + mm]) { len = mm; break; }
            slen[tid] = (unsigned char)len;
        }
        __syncthreads();

        if (tid == 0) {   // sequential scan -> row map
            for (int q = 0; q < NM; q++) srow[q] = -1;
            int idx = 0;
            for (int t = 0; t < NT; t++) {
                int len = slen[t];
                if (len > NM - idx) len = NM - idx;
                for (int k = 0; k < len; k++)
                    srow[idx + k] = (short)((t << 8) | k);
                idx += len;
            }
        }
        __syncthreads();

        const int code = srow[m];
        if (code == m) continue;   // speculation (t=0, ml=m) was correct: done

        float4* dst = reinterpret_cast<float4*>(
            out + ((size_t)b * NM + m) * NV + chunk * CHUNK);

        if (code < 0) {            // row never written by the scan: zero it
            const float4 z = make_float4(0.f, 0.f, 0.f, 0.f);
            #pragma unroll 2
            for (int jj = 0; jj < NITER; jj++) {
                const int i = tid + jj * 128;
                if (i < CHUNK4) __stcs(dst + i, z);
            }
        } else {                   // rare: recompute with the mapped (t, ml)
            const int t  = code >> 8;
            const int ml = code & 255;
            const int S  = __ldg(&spans[b]);

            float ws[NS];
            #pragma unroll
            for (int s = 0; s < NS; s++)
                ws[s] = __ldg(&tmpl[((size_t)b * NT + t) * (NSFULL + 1) + s + 1]);
            const float w0 = __ldg(&tmpl[((size_t)b * NT + t) * (NSFULL + 1)]);

            const float4* pc = reinterpret_cast<const float4*>(
                in + ((size_t)b * NSFULL * NM + ml) * NV + chunk * CHUNK);

            switch (S) {
                case 0: phase_c_body<0>(pc, dst, ws, w0, ml, chunk); break;
                case 1: phase_c_body<1>(pc, dst, ws, w0, ml, chunk); break;
                case 2: phase_c_body<2>(pc, dst, ws, w0, ml, chunk); break;
                case 3: phase_c_body<3>(pc, dst, ws, w0, ml, chunk); break;
                case 4: phase_c_body<4>(pc, dst, ws, w0, ml, chunk); break;
                default: phase_c_body<5>(pc, dst, ws, w0, ml, chunk); break;
            }
        }
    }
}

// ---------------------------------------------------------------------------
extern "C" void kernel_launch(void* const* d_in, const int* in_sizes, int n_in,
                              void* d_out, int out_size) {
    const float* in    = (const float*)d_in[0];  // [8,6,64,32000] f32
    const float* tmpl  = (const float*)d_in[1];  // [8,8,7] f32
    const int*   spans = (const int*)d_in[2];    // [8] i32
    float*       out   = (float*)d_out;          // [8,64,32000] f32

    dim3 grid(NM, 2, VSPLIT);  // 1024 blocks, exactly one resident wave
    fused_kernel<<<grid, 128>>>(in, tmpl, spans, out);
}

// round 15
// speedup vs baseline: 2.2952x; 1.1870x over previous
#include <cuda_runtime.h>
#include <math.h>

#define NB 8       // batch
#define NS 5       // max slabs reachable (spans in [0,5])
#define NSFULL 6   // slab dimension of the input tensor
#define NM 64      // M
#define NV 32000   // vocab
#define NT 8       // template length
#define VSPLIT 8
#define CHUNK  (NV / VSPLIT)   // 4000 floats
#define CHUNK4 (CHUNK / 4)     // 1000 float4
#define NITER  ((CHUNK4 + 127) / 128)   // 8
#define SSTRIDE4 ((NM * NV) / 4)        // float4 stride between slabs
#define NBLK   1024                     // all co-resident (128 thr, <=7/SM)
#define NPAIR  (NB / 2)                 // 4 batch pairs

// packed f32x2 helpers (Blackwell FFMA2 — only reachable via PTX)
#define PACK2(d, lo, hi) \
    asm("mov.b64 %0, {%1, %2};" : "=l"(d) : "f"(lo), "f"(hi))
#define UNPACK2(lo, hi, s) \
    asm("mov.b64 {%0, %1}, %2;" : "=f"(lo), "=f"(hi) : "l"(s))
#define FMA2(d, a, b, c) \
    asm("fma.rn.f32x2 %0, %1, %2, %3;" : "=l"(d) : "l"(a), "l"(b), "l"(c))

// tiny scratch (__device__ globals, no runtime allocation)
__device__ float    g_pmax[NB * NT * NM * VSPLIT];  // per-chunk partial max
__device__ float    g_out0[NB * NT * NM];           // out[b,t,m,0] (+pad)
__device__ unsigned g_count;                        // barrier arrivals (self-resets)
__device__ unsigned g_sense;                        // barrier sense (monotonic)

// ---------------------------------------------------------------------------
// Grid-wide barrier (all NBLK blocks co-resident; launch_bounds(128,7) =>
// 148*7 = 1036 >= 1024). Sense monotonic (replay-safe); count self-resets.
// ---------------------------------------------------------------------------
__device__ __forceinline__ void grid_barrier() {
    __syncthreads();
    __threadfence();
    if (threadIdx.x == 0) {
        const unsigned s0 = *(volatile unsigned*)&g_sense;
        const unsigned v  = atomicAdd(&g_count, 1);
        if (v == NBLK - 1) {
            g_count = 0;
            __threadfence();
            atomicAdd(&g_sense, 1);
        } else {
            while (*(volatile unsigned*)&g_sense == s0) { __nanosleep(64); }
        }
    }
    __syncthreads();
    __threadfence();
}

// ---------------------------------------------------------------------------
// Phase A body, compile-time S, t-packed f32x2 accumulation.
// wp[tp][s] packs (w[tp][s], w[tp+4][s]); acc[tp][c] packs (out_tp, out_tp+4)
// for vector component c. Per-lane rounding identical to scalar fmaf.
// ---------------------------------------------------------------------------
template <int S>
__device__ __forceinline__ void phase_a_body(
    const float4* __restrict__ p0,
    const unsigned long long (&wp)[4][NS], float (&maxv)[NT]) {

    const int tid = threadIdx.x;
    #pragma unroll
    for (int t = 0; t < NT; t++) maxv[t] = -INFINITY;

    #pragma unroll 2
    for (int j = 0; j < NITER; j++) {
        const int i = tid + j * 128;
        if (i < CHUNK4) {
            float4 x[S > 0 ? S : 1];
            #pragma unroll
            for (int s = 0; s < S; s++) x[s] = p0[i + s * SSTRIDE4];

            unsigned long long acc[4][4];
            #pragma unroll
            for (int tp = 0; tp < 4; tp++)
                #pragma unroll
                for (int c = 0; c < 4; c++) acc[tp][c] = 0ull;  // (0.f, 0.f)

            #pragma unroll
            for (int s = 0; s < S; s++) {
                unsigned long long vx, vy, vz, vw;
                PACK2(vx, x[s].x, x[s].x);
                PACK2(vy, x[s].y, x[s].y);
                PACK2(vz, x[s].z, x[s].z);
                PACK2(vw, x[s].w, x[s].w);
                #pragma unroll
                for (int tp = 0; tp < 4; tp++) {
                    const unsigned long long w = wp[tp][s];
                    FMA2(acc[tp][0], vx, w, acc[tp][0]);
                    FMA2(acc[tp][1], vy, w, acc[tp][1]);
                    FMA2(acc[tp][2], vz, w, acc[tp][2]);
                    FMA2(acc[tp][3], vw, w, acc[tp][3]);
                }
            }

            #pragma unroll
            for (int tp = 0; tp < 4; tp++) {
                float lo0, hi0, lo1, hi1, lo2, hi2, lo3, hi3;
                UNPACK2(lo0, hi0, acc[tp][0]);
                UNPACK2(lo1, hi1, acc[tp][1]);
                UNPACK2(lo2, hi2, acc[tp][2]);
                UNPACK2(lo3, hi3, acc[tp][3]);
                maxv[tp]     = fmaxf(maxv[tp],
                                     fmaxf(fmaxf(lo0, lo1), fmaxf(lo2, lo3)));
                maxv[tp + 4] = fmaxf(maxv[tp + 4],
                                     fmaxf(fmaxf(hi0, hi1), fmaxf(hi2, hi3)));
            }
        }
    }
}

// ---------------------------------------------------------------------------
// Phase C body, compile-time S, streaming stores (unchanged from R8).
// ---------------------------------------------------------------------------
template <int S>
__device__ __forceinline__ void phase_c_body(
    const float4* __restrict__ p0, float4* __restrict__ dst,
    const float (&ws)[NS], float w0, int ml, int chunk) {

    const int tid = threadIdx.x;
    #pragma unroll 2
    for (int j = 0; j < NITER; j++) {
        const int i = tid + j * 128;
        if (i < CHUNK4) {
            float4 x[S > 0 ? S : 1];
            #pragma unroll
            for (int s = 0; s < S; s++) x[s] = p0[i + s * SSTRIDE4];

            float4 acc = make_float4(0.f, 0.f, 0.f, 0.f);
            #pragma unroll
            for (int s = 0; s < S; s++) {
                const float wv = ws[s];
                acc.x = fmaf(wv, x[s].x, acc.x);
                acc.y = fmaf(wv, x[s].y, acc.y);
                acc.z = fmaf(wv, x[s].z, acc.z);
                acc.w = fmaf(wv, x[s].w, acc.w);
            }
            if (chunk == 0 && i == 0 && ml == 0) acc.x += w0;  // pad one-hot
            __stcs(dst + i, acc);
        }
    }
}

// ---------------------------------------------------------------------------
// Fused persistent kernel: A_p -> barrier -> C_p per batch pair (R8 layout).
// argmax==0  <=>  out[v=0] attains the max (argmax ties go to index 0)
// ---------------------------------------------------------------------------
__global__ void __launch_bounds__(128, 7)
fused_kernel(const float* __restrict__ in, const float* __restrict__ tmpl,
             const int* __restrict__ spans, float* __restrict__ out) {
    const int m     = blockIdx.x;   // row index in A, output row j in C
    const int yb    = blockIdx.y;   // 0/1 within the pair
    const int chunk = blockIdx.z;
    const int tid   = threadIdx.x;

    __shared__ float ssw[NT][NS];
    __shared__ float ssw0[NT];
    __shared__ int   sS;
    __shared__ float spart[4][NT];
    __shared__ unsigned char sflags[NT * NM];
    __shared__ unsigned char slen[NT];
    __shared__ short         srow[NM];

    for (int p = 0; p < NPAIR; p++) {
        const int b = 2 * p + yb;
        __syncthreads();   // protect shared arrays across iterations

        // ---- stage weights for batch b ----
        if (tid == 0) sS = spans[b];
        if (tid < NT * NSFULL) {
            int t = tid / NSFULL, s = tid % NSFULL;
            float v = tmpl[((size_t)b * NT + t) * (NSFULL + 1) + s];
            if (s == 0) ssw0[t] = v;
            else        ssw[t][s - 1] = v;
        }
        __syncthreads();
        const int S = sS;

        // packed weight pairs: wp[tp][s] = (w[tp][s], w[tp+4][s])
        unsigned long long wp[4][NS];
        #pragma unroll
        for (int tp = 0; tp < 4; tp++)
            #pragma unroll
            for (int s = 0; s < NS; s++)
                PACK2(wp[tp][s], ssw[tp][s], ssw[tp + 4][s]);

        const float4* pa = reinterpret_cast<const float4*>(
            in + ((size_t)b * NSFULL * NM + m) * NV + chunk * CHUNK);

        // ---- phase A ----
        float maxv[NT];
        switch (S) {
            case 0: phase_a_body<0>(pa, wp, maxv); break;
            case 1: phase_a_body<1>(pa, wp, maxv); break;
            case 2: phase_a_body<2>(pa, wp, maxv); break;
            case 3: phase_a_body<3>(pa, wp, maxv); break;
            case 4: phase_a_body<4>(pa, wp, maxv); break;
            default: phase_a_body<5>(pa, wp, maxv); break;
        }

        #pragma unroll
        for (int t = 0; t < NT; t++) {
            float v = maxv[t];
            #pragma unroll
            for (int off = 16; off > 0; off >>= 1)
                v = fmaxf(v, __shfl_xor_sync(0xFFFFFFFFu, v, off));
            maxv[t] = v;
        }
        const int warp = tid >> 5, lane = tid & 31;
        if (lane == 0) {
            #pragma unroll
            for (int t = 0; t < NT; t++) spart[warp][t] = maxv[t];
        }
        __syncthreads();
        if (tid < NT) {
            const int t = tid;
            float mx = fmaxf(fmaxf(spart[0][t], spart[1][t]),
                             fmaxf(spart[2][t], spart[3][t]));
            g_pmax[(((size_t)b * NT + t) * NM + m) * VSPLIT + chunk] = mx;
        }

        // cold epilogue: out[b,t,m,0] (dot + pad one-hot), chunk 0 / thread 0
        if (chunk == 0 && tid == 0) {
            float x0[NS];
            for (int s = 0; s < S; s++)
                x0[s] = __ldg(reinterpret_cast<const float*>(pa + s * SSTRIDE4));
            #pragma unroll
            for (int t = 0; t < NT; t++) {
                float v = 0.f;
                for (int s = 0; s < S; s++) v = fmaf(ssw[t][s], x0[s], v);
                if (m == 0) v += ssw0[t];
                g_out0[((size_t)b * NT + t) * NM + m] = v;
            }
        }

        // ---- all blocks' maxes must land before anyone scans ----
        grid_barrier();

        // ---- phase C: flags + scan (redundant per block, L2-hot) ----
        #pragma unroll
        for (int k = 0; k < 4; k++) {
            const int tm  = tid + 128 * k;               // t*64 + mm
            const int idx = b * NT * NM + tm;
            const float4* pm =
                reinterpret_cast<const float4*>(&g_pmax[(size_t)idx * VSPLIT]);
            const float4 a = __ldcg(pm), c = __ldcg(pm + 1);
            float mx = fmaxf(fmaxf(fmaxf(a.x, a.y), fmaxf(a.z, a.w)),
                             fmaxf(fmaxf(c.x, c.y), fmaxf(c.z, c.w)));
            sflags[tm] = (__ldcg(&g_out0[idx]) >= mx) ? 1 : 0;
        }
        __syncthreads();

        if (tid < NT) {   // first-zero position per t
            int len = NM;
            for (int mm = 0; mm < NM; mm++)
                if (sflags[tid * NM + mm]) { len = mm; break; }
            slen[tid] = (unsigned char)len;
        }
        __syncthreads();

        if (tid == 0) {   // sequential scan -> row map
            for (int q = 0; q < NM; q++) srow[q] = -1;
            int idx = 0;
            for (int t = 0; t < NT; t++) {
                int len = slen[t];
                if (len > NM - idx) len = NM - idx;
                for (int k = 0; k < len; k++)
                    srow[idx + k] = (short)((t << 8) | k);
                idx += len;
            }
        }
        __syncthreads();

        // ---- phase C: materialize this block's output row (j = m) ----
        float4* dst = reinterpret_cast<float4*>(
            out + ((size_t)b * NM + m) * NV + chunk * CHUNK);
        const int code = srow[m];

        if (code < 0) {
            const float4 z = make_float4(0.f, 0.f, 0.f, 0.f);
            #pragma unroll 2
            for (int jj = 0; jj < NITER; jj++) {
                const int i = tid + jj * 128;
                if (i < CHUNK4) __stcs(dst + i, z);
            }
        } else {
            const int t  = code >> 8;
            const int ml = code & 255;

            float ws[NS];
            #pragma unroll
            for (int s = 0; s < NS; s++)
                ws[s] = tmpl[((size_t)b * NT + t) * (NSFULL + 1) + s + 1];
            const float w0 = tmpl[((size_t)b * NT + t) * (NSFULL + 1) + 0];

            const float4* pc = reinterpret_cast<const float4*>(
                in + ((size_t)b * NSFULL * NM + ml) * NV + chunk * CHUNK);

            switch (S) {
                case 0: phase_c_body<0>(pc, dst, ws, w0, ml, chunk); break;
                case 1: phase_c_body<1>(pc, dst, ws, w0, ml, chunk); break;
                case 2: phase_c_body<2>(pc, dst, ws, w0, ml, chunk); break;
                case 3: phase_c_body<3>(pc, dst, ws, w0, ml, chunk); break;
                case 4: phase_c_body<4>(pc, dst, ws, w0, ml, chunk); break;
                default: phase_c_body<5>(pc, dst, ws, w0, ml, chunk); break;
            }
        }
        // no barrier before next A: g_pmax/g_out0 indices disjoint across
        // pairs; shared arrays protected by loop-top __syncthreads.
    }
}

// ---------------------------------------------------------------------------
extern "C" void kernel_launch(void* const* d_in, const int* in_sizes, int n_in,
                              void* d_out, int out_size) {
    const float* in    = (const float*)d_in[0];  // [8,6,64,32000] f32
    const float* tmpl  = (const float*)d_in[1];  // [8,8,7] f32
    const int*   spans = (const int*)d_in[2];    // [8] i32
    float*       out   = (float*)d_out;          // [8,64,32000] f32

    dim3 grid(NM, 2, VSPLIT);  // 1024 blocks, exactly one resident wave
    fused_kernel<<<grid, 128>>>(in, tmpl, spans, out);
}